// round 1
// baseline (speedup 1.0000x reference)
#include <cuda_runtime.h>

// ---------------------------------------------------------------------------
// MGPATH Sinkhorn-OT head, fused single persistent kernel.
//   inputs:  img [65536,1,1024] f32 (L2-normalized), txt [4,2,1024] f32,
//            logit_scale [1] f32
//   output:  [1,2] f32
// ---------------------------------------------------------------------------

#define M_ROWS 65536
#define D_DIM  1024
#define NBLK   128
#define NTHR   512
#define SINK_MAX_ITER 100
#define SINK_THRESH 0.01f

// cross-block state (no allocations allowed -> __device__ globals)
__device__ volatile float    g_part[NBLK * 16];
__device__ volatile float    g_cnew[8];
__device__ volatile int      g_stop;
__device__ unsigned          g_cnt;
__device__ volatile unsigned g_gen;

__global__ void mg_init() { g_cnt = 0u; g_gen = 0u; g_stop = 0; }

// sense-reversing grid barrier; safe because all NBLK blocks are co-resident
__device__ __forceinline__ void grid_barrier(unsigned &mygen) {
    __syncthreads();
    if (threadIdx.x == 0) {
        __threadfence();
        unsigned prev = atomicAdd(&g_cnt, 1u);
        if (prev == NBLK - 1) {
            g_cnt = 0u;
            __threadfence();
            g_gen = mygen + 1u;
        } else {
            while (g_gen == mygen) { __nanosleep(32); }
        }
        __threadfence();
    }
    __syncthreads();
    mygen++;
}

// reduce NV floats across the 512-thread block; result valid in thread 0
template <int NV>
__device__ __forceinline__ void block_reduce(float* vals, float* red) {
    #pragma unroll
    for (int i = 0; i < NV; i++) {
        #pragma unroll
        for (int o = 16; o > 0; o >>= 1)
            vals[i] += __shfl_down_sync(0xffffffffu, vals[i], o);
    }
    int w = threadIdx.x >> 5, l = threadIdx.x & 31;
    if (l == 0) {
        #pragma unroll
        for (int i = 0; i < NV; i++) red[i * 16 + w] = vals[i];
    }
    __syncthreads();
    if (threadIdx.x < 32) {
        #pragma unroll
        for (int i = 0; i < NV; i++) {
            float x = (l < 16) ? red[i * 16 + l] : 0.0f;
            #pragma unroll
            for (int o = 8; o > 0; o >>= 1)
                x += __shfl_down_sync(0xffffffffu, x, o);
            vals[i] = x;
        }
    }
    __syncthreads();
}

__global__ void __launch_bounds__(NTHR)
mg_fused(const float* __restrict__ img,
         const float* __restrict__ txt,
         const float* __restrict__ ls,
         float* __restrict__ out) {
    // txtS[d][v] transposed layout: v = beta*4 + n, element = txt[(n*2+beta)*D + d]
    __shared__ float txtS[D_DIM * 8];
    __shared__ float red[9 * 16];

    const int tid = threadIdx.x;
    const int m = blockIdx.x * NTHR + tid;   // exactly one row per thread

    for (int i = tid; i < D_DIM * 8; i += NTHR) {
        int d = i >> 3, v = i & 7;
        int n = v & 3, c = v >> 2;           // beta = c
        txtS[i] = txt[(n * 2 + c) * D_DIM + d];
    }
    __syncthreads();

    // ---- GEMM: sim[v] = sum_d img[m][d] * txtS[d][v], packed f32x2 FMAs ----
    unsigned long long acc[4] = {0ull, 0ull, 0ull, 0ull}; // (v0,v1)(v2,v3)(v4,v5)(v6,v7)
    const float4* row = reinterpret_cast<const float4*>(img) + (size_t)m * (D_DIM / 4);
    const ulonglong2* ts2 = reinterpret_cast<const ulonglong2*>(txtS);
    #pragma unroll 4
    for (int j = 0; j < D_DIM / 4; j++) {
        float4 a = __ldg(&row[j]);
        float xs[4] = {a.x, a.y, a.z, a.w};
        #pragma unroll
        for (int e = 0; e < 4; e++) {
            unsigned long long xx;
            asm("mov.b64 %0, {%1, %1};" : "=l"(xx) : "f"(xs[e]));
            ulonglong2 tA = ts2[(j * 4 + e) * 2 + 0];
            ulonglong2 tB = ts2[(j * 4 + e) * 2 + 1];
            asm("fma.rn.f32x2 %0, %1, %2, %0;" : "+l"(acc[0]) : "l"(xx), "l"(tA.x));
            asm("fma.rn.f32x2 %0, %1, %2, %0;" : "+l"(acc[1]) : "l"(xx), "l"(tA.y));
            asm("fma.rn.f32x2 %0, %1, %2, %0;" : "+l"(acc[2]) : "l"(xx), "l"(tB.x));
            asm("fma.rn.f32x2 %0, %1, %2, %0;" : "+l"(acc[3]) : "l"(xx), "l"(tB.y));
        }
    }
    float sim[8];
    #pragma unroll
    for (int p = 0; p < 4; p++)
        asm("mov.b64 {%0, %1}, %2;" : "=f"(sim[p * 2]), "=f"(sim[p * 2 + 1]) : "l"(acc[p]));

    // K = exp(-(1 - sim)/0.1) ; lives entirely in registers
    float Kv[8];
    #pragma unroll
    for (int i = 0; i < 8; i++) Kv[i] = expf((sim[i] - 1.0f) * 10.0f);

    const float uu = 1.0f / (float)M_ROWS;   // u = 1/M
    float cm[8], cp[8];                      // c_{t-1}, c_{t-2}
    #pragma unroll
    for (int i = 0; i < 8; i++) { cm[i] = 1.0f; cp[i] = 1.0f; }

    // ---- Sinkhorn loop (c-only state; r recomputed from c each sweep) ----
    unsigned mygen = 0;
    int t = 0;
    for (;;) {
        t++;
        float vals[9];
        float err = 0.0f;
        float rr[2];
        #pragma unroll
        for (int b = 0; b < 2; b++) {
            float s = 0.0f, s2 = 0.0f;
            #pragma unroll
            for (int n = 0; n < 4; n++) {
                s  = fmaf(Kv[b * 4 + n], cm[b * 4 + n], s);
                s2 = fmaf(Kv[b * 4 + n], cp[b * 4 + n], s2);
            }
            float r    = uu / s;
            float rold = (t == 1) ? 1.0f : uu / s2;   // r0 = ones
            rr[b] = r;
            err += fabsf(r - rold);
        }
        #pragma unroll
        for (int b = 0; b < 2; b++) {
            #pragma unroll
            for (int n = 0; n < 4; n++)
                vals[b * 4 + n] = Kv[b * 4 + n] * rr[b];  // column sums for c
        }
        vals[8] = err;

        block_reduce<9>(vals, red);
        if (tid == 0) {
            #pragma unroll
            for (int i = 0; i < 9; i++) g_part[blockIdx.x * 16 + i] = vals[i];
        }
        grid_barrier(mygen);

        if (blockIdx.x == 0) {
            float pv[9];
            #pragma unroll
            for (int i = 0; i < 9; i++)
                pv[i] = (tid < NBLK) ? g_part[tid * 16 + i] : 0.0f;
            block_reduce<9>(pv, red);
            if (tid == 0) {
                float e = pv[8] * (1.0f / (2.0f * (float)M_ROWS));
                #pragma unroll
                for (int i = 0; i < 8; i++) g_cnew[i] = 0.25f / pv[i]; // v = 1/N
                g_stop = (e < SINK_THRESH || t >= SINK_MAX_ITER) ? 1 : 0;
            }
        }
        grid_barrier(mygen);

        int stop = g_stop;
        #pragma unroll
        for (int i = 0; i < 8; i++) { cp[i] = cm[i]; cm[i] = g_cnew[i]; }
        if (stop) break;
    }

    // ---- final: sim_op[b] = sum_m r_T[m] * sum_n c_T[n] K sim,  r_T from cp ----
    float ov[2];
    #pragma unroll
    for (int b = 0; b < 2; b++) {
        float s = 0.0f, a = 0.0f;
        #pragma unroll
        for (int n = 0; n < 4; n++) {
            s = fmaf(Kv[b * 4 + n], cp[b * 4 + n], s);
            a = fmaf(cm[b * 4 + n] * Kv[b * 4 + n], sim[b * 4 + n], a);
        }
        ov[b] = (uu / s) * a;
    }
    block_reduce<2>(ov, red);
    if (tid == 0) {
        g_part[blockIdx.x * 16 + 0] = ov[0];
        g_part[blockIdx.x * 16 + 1] = ov[1];
    }
    grid_barrier(mygen);
    if (blockIdx.x == 0) {
        float pv[2];
        pv[0] = (tid < NBLK) ? g_part[tid * 16 + 0] : 0.0f;
        pv[1] = (tid < NBLK) ? g_part[tid * 16 + 1] : 0.0f;
        block_reduce<2>(pv, red);
        if (tid == 0) {
            float sc = expf(ls[0]);
            out[0] = sc * pv[0];
            out[1] = sc * pv[1];
        }
    }
}

extern "C" void kernel_launch(void* const* d_in, const int* in_sizes, int n_in,
                              void* d_out, int out_size) {
    const float* img = (const float*)d_in[0];
    const float* txt = (const float*)d_in[1];
    const float* ls  = (const float*)d_in[2];
    float* out = (float*)d_out;
    (void)in_sizes; (void)n_in; (void)out_size;

    mg_init<<<1, 1>>>();
    mg_fused<<<NBLK, NTHR>>>(img, txt, ls, out);
}

// round 2
// speedup vs baseline: 1.4862x; 1.4862x over previous
#include <cuda_runtime.h>

// ---------------------------------------------------------------------------
// MGPATH Sinkhorn-OT head, fused single persistent kernel. R2:
// warp-cooperative coalesced GEMM (nL=4 LDG, conflict-free lane-varying LDS,
// 4-row txt amortization, shfl reduction) + register-resident Sinkhorn.
// ---------------------------------------------------------------------------

#define M_ROWS 65536
#define D_DIM  1024
#define NBLK   128
#define NTHR   512
#define SINK_MAX_ITER 100
#define SINK_THRESH 0.01f

__device__ volatile float    g_part[NBLK * 16];
__device__ volatile float    g_cnew[8];
__device__ volatile int      g_stop;
__device__ unsigned          g_cnt;
__device__ volatile unsigned g_gen;

__global__ void mg_init() { g_cnt = 0u; g_gen = 0u; g_stop = 0; }

// sense-reversing grid barrier; all NBLK blocks are co-resident (1/SM)
__device__ __forceinline__ void grid_barrier(unsigned &mygen) {
    __syncthreads();
    if (threadIdx.x == 0) {
        __threadfence();
        unsigned prev = atomicAdd(&g_cnt, 1u);
        if (prev == NBLK - 1) {
            g_cnt = 0u;
            __threadfence();
            g_gen = mygen + 1u;
        } else {
            while (g_gen == mygen) { __nanosleep(32); }
        }
        __threadfence();
    }
    __syncthreads();
    mygen++;
}

template <int NV>
__device__ __forceinline__ void block_reduce(float* vals, float* red) {
    #pragma unroll
    for (int i = 0; i < NV; i++) {
        #pragma unroll
        for (int o = 16; o > 0; o >>= 1)
            vals[i] += __shfl_down_sync(0xffffffffu, vals[i], o);
    }
    int w = threadIdx.x >> 5, l = threadIdx.x & 31;
    if (l == 0) {
        #pragma unroll
        for (int i = 0; i < NV; i++) red[i * 16 + w] = vals[i];
    }
    __syncthreads();
    if (threadIdx.x < 32) {
        #pragma unroll
        for (int i = 0; i < NV; i++) {
            float x = (l < 16) ? red[i * 16 + l] : 0.0f;
            #pragma unroll
            for (int o = 8; o > 0; o >>= 1)
                x += __shfl_down_sync(0xffffffffu, x, o);
            vals[i] = x;
        }
    }
    __syncthreads();
}

__global__ void __launch_bounds__(NTHR, 1)
mg_fused(const float* __restrict__ img,
         const float* __restrict__ txt,
         const float* __restrict__ ls,
         float* __restrict__ out) {
    // v-major txt: txtS[v*1024 + d], v = c*4 + n, value = txt[(n*2+c)*D + d]
    __shared__ float txtS[8 * D_DIM];
    __shared__ float red[9 * 16];

    const int tid  = threadIdx.x;
    const int lane = tid & 31;
    const int wid  = tid >> 5;

    for (int i = tid; i < 8 * D_DIM; i += NTHR) {
        int v = i >> 10, d = i & 1023;
        int n = v & 3, c = v >> 2;
        txtS[i] = txt[(n * 2 + c) * D_DIM + d];
    }
    __syncthreads();

    // warp owns 32 consecutive rows; lane i will end up holding row base+i
    const int warpRowBase = blockIdx.x * NTHR + wid * 32;
    const float4* img4 = reinterpret_cast<const float4*>(img);
    const ulonglong2* ts2 = reinterpret_cast<const ulonglong2*>(txtS);

    float simv[8];
    #pragma unroll
    for (int v = 0; v < 8; v++) simv[v] = 0.0f;

    // ---- cooperative GEMM: 8 passes x 4 rows; lanes split D, coalesced ----
    #pragma unroll 1
    for (int pass = 0; pass < 8; pass++) {
        unsigned long long acc[4][8];
        #pragma unroll
        for (int g = 0; g < 4; g++)
            #pragma unroll
            for (int v = 0; v < 8; v++) acc[g][v] = 0ull;

        const int r0 = warpRowBase + pass * 4;
        #pragma unroll 2
        for (int jj = 0; jj < 8; jj++) {
            // lane's dims this step: d = jj*128 + lane*4 .. +3
            unsigned long long ilo[4], ihi[4];
            #pragma unroll
            for (int g = 0; g < 4; g++) {
                float4 a = img4[(size_t)(r0 + g) * (D_DIM / 4) + jj * 32 + lane];
                asm("mov.b64 %0, {%1, %2};" : "=l"(ilo[g]) : "f"(a.x), "f"(a.y));
                asm("mov.b64 %0, {%1, %2};" : "=l"(ihi[g]) : "f"(a.z), "f"(a.w));
            }
            #pragma unroll
            for (int v = 0; v < 8; v++) {
                ulonglong2 tv = ts2[v * 256 + jj * 32 + lane];  // txtS[v][d..d+3]
                #pragma unroll
                for (int g = 0; g < 4; g++) {
                    asm("fma.rn.f32x2 %0, %1, %2, %0;" : "+l"(acc[g][v]) : "l"(ilo[g]), "l"(tv.x));
                    asm("fma.rn.f32x2 %0, %1, %2, %0;" : "+l"(acc[g][v]) : "l"(ihi[g]), "l"(tv.y));
                }
            }
        }
        // reduce partials across lanes; deposit row (pass*4+g) on its lane
        #pragma unroll
        for (int g = 0; g < 4; g++) {
            float p[8];
            #pragma unroll
            for (int v = 0; v < 8; v++) {
                float x, y;
                asm("mov.b64 {%0, %1}, %2;" : "=f"(x), "=f"(y) : "l"(acc[g][v]));
                p[v] = x + y;
            }
            #pragma unroll
            for (int o = 16; o > 0; o >>= 1)
                #pragma unroll
                for (int v = 0; v < 8; v++)
                    p[v] += __shfl_xor_sync(0xffffffffu, p[v], o);
            if (lane == pass * 4 + g) {
                #pragma unroll
                for (int v = 0; v < 8; v++) simv[v] = p[v];
            }
        }
    }

    // K = exp(-(1 - sim)/0.1), register-resident; this lane's row = base+lane
    float Kv[8];
    #pragma unroll
    for (int i = 0; i < 8; i++) Kv[i] = expf((simv[i] - 1.0f) * 10.0f);

    const float uu = 1.0f / (float)M_ROWS;
    float cm[8], cp[8];
    #pragma unroll
    for (int i = 0; i < 8; i++) { cm[i] = 1.0f; cp[i] = 1.0f; }

    // ---- Sinkhorn loop (c-only state; r recomputed from c each sweep) ----
    unsigned mygen = 0;
    int t = 0;
    for (;;) {
        t++;
        float vals[9];
        float err = 0.0f;
        float rr[2];
        #pragma unroll
        for (int b = 0; b < 2; b++) {
            float s = 0.0f, s2 = 0.0f;
            #pragma unroll
            for (int n = 0; n < 4; n++) {
                s  = fmaf(Kv[b * 4 + n], cm[b * 4 + n], s);
                s2 = fmaf(Kv[b * 4 + n], cp[b * 4 + n], s2);
            }
            float r    = uu / s;
            float rold = (t == 1) ? 1.0f : uu / s2;   // r0 = ones
            rr[b] = r;
            err += fabsf(r - rold);
        }
        #pragma unroll
        for (int b = 0; b < 2; b++)
            #pragma unroll
            for (int n = 0; n < 4; n++)
                vals[b * 4 + n] = Kv[b * 4 + n] * rr[b];
        vals[8] = err;

        block_reduce<9>(vals, red);
        if (tid == 0) {
            #pragma unroll
            for (int i = 0; i < 9; i++) g_part[blockIdx.x * 16 + i] = vals[i];
        }
        grid_barrier(mygen);

        if (blockIdx.x == 0) {
            float pv[9];
            #pragma unroll
            for (int i = 0; i < 9; i++)
                pv[i] = (tid < NBLK) ? g_part[tid * 16 + i] : 0.0f;
            block_reduce<9>(pv, red);
            if (tid == 0) {
                float e = pv[8] * (1.0f / (2.0f * (float)M_ROWS));
                #pragma unroll
                for (int i = 0; i < 8; i++) g_cnew[i] = 0.25f / pv[i];
                g_stop = (e < SINK_THRESH || t >= SINK_MAX_ITER) ? 1 : 0;
            }
        }
        grid_barrier(mygen);

        int stop = g_stop;
        #pragma unroll
        for (int i = 0; i < 8; i++) { cp[i] = cm[i]; cm[i] = g_cnew[i]; }
        if (stop) break;
    }

    // ---- final: sim_op[b] = sum_m r_T[m] * sum_n c_T[n] K[m,n] sim[m,n] ----
    float ov[2];
    #pragma unroll
    for (int b = 0; b < 2; b++) {
        float s = 0.0f, a = 0.0f;
        #pragma unroll
        for (int n = 0; n < 4; n++) {
            s = fmaf(Kv[b * 4 + n], cp[b * 4 + n], s);
            a = fmaf(cm[b * 4 + n] * Kv[b * 4 + n], simv[b * 4 + n], a);
        }
        ov[b] = (uu / s) * a;
    }
    block_reduce<2>(ov, red);
    if (tid == 0) {
        g_part[blockIdx.x * 16 + 0] = ov[0];
        g_part[blockIdx.x * 16 + 1] = ov[1];
    }
    grid_barrier(mygen);
    if (blockIdx.x == 0) {
        float pv[2];
        pv[0] = (tid < NBLK) ? g_part[tid * 16 + 0] : 0.0f;
        pv[1] = (tid < NBLK) ? g_part[tid * 16 + 1] : 0.0f;
        block_reduce<2>(pv, red);
        if (tid == 0) {
            float sc = expf(ls[0]);
            out[0] = sc * pv[0];
            out[1] = sc * pv[1];
        }
    }
}

extern "C" void kernel_launch(void* const* d_in, const int* in_sizes, int n_in,
                              void* d_out, int out_size) {
    const float* img = (const float*)d_in[0];
    const float* txt = (const float*)d_in[1];
    const float* ls  = (const float*)d_in[2];
    float* out = (float*)d_out;
    (void)in_sizes; (void)n_in; (void)out_size;

    mg_init<<<1, 1>>>();
    mg_fused<<<NBLK, NTHR>>>(img, txt, ls, out);
}

// round 3
// speedup vs baseline: 1.6260x; 1.0941x over previous
#include <cuda_runtime.h>

// ---------------------------------------------------------------------------
// MGPATH Sinkhorn-OT head, fused persistent kernel. R3:
// 148 blocks (full chip), multi-value butterfly reduction (31 shfl/pass),
// prefetch-1 pipelined coalesced GEMM, register-resident Sinkhorn.
// ---------------------------------------------------------------------------

#define M_ROWS 65536
#define D_DIM  1024
#define NBLK   148
#define NTHR   512
#define NWARP  16
#define NGROUPS 2048            // 65536 rows / 32 rows-per-warp-group
#define SINK_MAX_ITER 100
#define SINK_THRESH 0.01f

__device__ volatile float    g_part[NBLK * 16];
__device__ volatile float    g_cnew[8];
__device__ volatile int      g_stop;
__device__ unsigned          g_cnt;
__device__ volatile unsigned g_gen;

__global__ void mg_init() { g_cnt = 0u; g_gen = 0u; g_stop = 0; }

// sense-reversing grid barrier; all NBLK blocks co-resident (1/SM, 148 SMs)
__device__ __forceinline__ void grid_barrier(unsigned &mygen) {
    __syncthreads();
    if (threadIdx.x == 0) {
        __threadfence();
        unsigned prev = atomicAdd(&g_cnt, 1u);
        if (prev == NBLK - 1) {
            g_cnt = 0u;
            __threadfence();
            g_gen = mygen + 1u;
        } else {
            while (g_gen == mygen) { __nanosleep(32); }
        }
        __threadfence();
    }
    __syncthreads();
    mygen++;
}

template <int NV>
__device__ __forceinline__ void block_reduce(float* vals, float* red) {
    #pragma unroll
    for (int i = 0; i < NV; i++) {
        #pragma unroll
        for (int o = 16; o > 0; o >>= 1)
            vals[i] += __shfl_down_sync(0xffffffffu, vals[i], o);
    }
    int w = threadIdx.x >> 5, l = threadIdx.x & 31;
    if (l == 0) {
        #pragma unroll
        for (int i = 0; i < NV; i++) red[i * 16 + w] = vals[i];
    }
    __syncthreads();
    if (threadIdx.x < 32) {
        #pragma unroll
        for (int i = 0; i < NV; i++) {
            float x = (l < 16) ? red[i * 16 + l] : 0.0f;
            #pragma unroll
            for (int o = 8; o > 0; o >>= 1)
                x += __shfl_down_sync(0xffffffffu, x, o);
            vals[i] = x;
        }
    }
    __syncthreads();
}

__global__ void __launch_bounds__(NTHR, 1)
mg_fused(const float* __restrict__ img,
         const float* __restrict__ txt,
         const float* __restrict__ ls,
         float* __restrict__ out) {
    // v-major txt: txtS[v*1024 + d], v = c*4 + n, value = txt[(n*2+c)*D + d]
    __shared__ float txtS[8 * D_DIM];
    __shared__ float simP[NWARP * 32];
    __shared__ float red[9 * 16];

    const int tid  = threadIdx.x;
    const int lane = tid & 31;
    const int wid  = tid >> 5;

    for (int i = tid; i < 8 * D_DIM; i += NTHR) {
        int v = i >> 10, d = i & 1023;
        int n = v & 3, c = v >> 2;
        txtS[i] = txt[(n * 2 + c) * D_DIM + d];
    }
    __syncthreads();

    // round-robin row-group assignment over the full 148-block grid
    const int rg = wid * NBLK + blockIdx.x;
    const bool active = (rg < NGROUPS);

    const float4* img4 = reinterpret_cast<const float4*>(img);
    const ulonglong2* ts2 = reinterpret_cast<const ulonglong2*>(txtS);

    float simv[8] = {0.f, 0.f, 0.f, 0.f, 0.f, 0.f, 0.f, 0.f};

    if (active) {
        #pragma unroll 1
        for (int pass = 0; pass < 8; pass++) {
            const int r0 = rg * 32 + pass * 4;
            const float4* bp = img4 + (size_t)r0 * (D_DIM / 4) + lane;

            unsigned long long acc[4][8];
            #pragma unroll
            for (int g = 0; g < 4; g++)
                #pragma unroll
                for (int v = 0; v < 8; v++) acc[g][v] = 0ull;

            float4 cur[4];
            #pragma unroll
            for (int g = 0; g < 4; g++) cur[g] = __ldcs(bp + g * 256);

            #pragma unroll
            for (int jj = 0; jj < 8; jj++) {
                float4 nxt[4];
                if (jj < 7) {
                    #pragma unroll
                    for (int g = 0; g < 4; g++)
                        nxt[g] = __ldcs(bp + g * 256 + (jj + 1) * 32);
                }
                unsigned long long lo[4], hi[4];
                #pragma unroll
                for (int g = 0; g < 4; g++) {
                    asm("mov.b64 %0, {%1, %2};" : "=l"(lo[g]) : "f"(cur[g].x), "f"(cur[g].y));
                    asm("mov.b64 %0, {%1, %2};" : "=l"(hi[g]) : "f"(cur[g].z), "f"(cur[g].w));
                }
                #pragma unroll
                for (int v = 0; v < 8; v++) {
                    ulonglong2 tv = ts2[v * 256 + jj * 32 + lane];
                    #pragma unroll
                    for (int g = 0; g < 4; g++) {
                        asm("fma.rn.f32x2 %0, %1, %2, %0;" : "+l"(acc[g][v]) : "l"(lo[g]), "l"(tv.x));
                        asm("fma.rn.f32x2 %0, %1, %2, %0;" : "+l"(acc[g][v]) : "l"(hi[g]), "l"(tv.y));
                    }
                }
                #pragma unroll
                for (int g = 0; g < 4; g++) cur[g] = nxt[g];
            }

            // 32 partials (g*8+v), multi-value butterfly: 31 shfl total;
            // lane L ends holding fully-reduced value index L.
            float vals[32];
            #pragma unroll
            for (int g = 0; g < 4; g++)
                #pragma unroll
                for (int v = 0; v < 8; v++) {
                    float x, y;
                    asm("mov.b64 {%0, %1}, %2;" : "=f"(x), "=f"(y) : "l"(acc[g][v]));
                    vals[g * 8 + v] = x + y;
                }
            #pragma unroll
            for (int h = 16; h >= 1; h >>= 1) {
                bool up = (lane & h) != 0;
                #pragma unroll
                for (int i = 0; i < h; i++) {
                    float keep = up ? vals[i + h] : vals[i];
                    float send = up ? vals[i]     : vals[i + h];
                    vals[i] = keep + __shfl_xor_sync(0xffffffffu, send, h);
                }
            }
            // transpose via tiny smem slab: row (pass*4+g) gets its 8 v's
            simP[wid * 32 + lane] = vals[0];
            __syncwarp();
            if ((lane >> 2) == pass) {
                int base = wid * 32 + (lane & 3) * 8;
                float4 s0 = *reinterpret_cast<float4*>(&simP[base]);
                float4 s1 = *reinterpret_cast<float4*>(&simP[base + 4]);
                simv[0] = s0.x; simv[1] = s0.y; simv[2] = s0.z; simv[3] = s0.w;
                simv[4] = s1.x; simv[5] = s1.y; simv[6] = s1.z; simv[7] = s1.w;
            }
            __syncwarp();
        }
    }

    // K = exp(-(1 - sim)/0.1); lane owns row rg*32 + lane
    float Kv[8];
    #pragma unroll
    for (int i = 0; i < 8; i++) Kv[i] = active ? expf((simv[i] - 1.0f) * 10.0f) : 0.0f;

    const float uu = 1.0f / (float)M_ROWS;
    float cm[8], cp[8];
    #pragma unroll
    for (int i = 0; i < 8; i++) { cm[i] = 1.0f; cp[i] = 1.0f; }

    // ---- Sinkhorn loop (c-only state; r recomputed from c each sweep) ----
    unsigned mygen = 0;
    int t = 0;
    for (;;) {
        t++;
        float vals9[9];
        if (active) {
            float err = 0.0f;
            float rr[2];
            #pragma unroll
            for (int b = 0; b < 2; b++) {
                float s = 0.0f, s2 = 0.0f;
                #pragma unroll
                for (int n = 0; n < 4; n++) {
                    s  = fmaf(Kv[b * 4 + n], cm[b * 4 + n], s);
                    s2 = fmaf(Kv[b * 4 + n], cp[b * 4 + n], s2);
                }
                float r    = uu / s;
                float rold = (t == 1) ? 1.0f : uu / s2;   // r0 = ones
                rr[b] = r;
                err += fabsf(r - rold);
            }
            #pragma unroll
            for (int b = 0; b < 2; b++)
                #pragma unroll
                for (int n = 0; n < 4; n++)
                    vals9[b * 4 + n] = Kv[b * 4 + n] * rr[b];
            vals9[8] = err;
        } else {
            #pragma unroll
            for (int i = 0; i < 9; i++) vals9[i] = 0.0f;
        }

        block_reduce<9>(vals9, red);
        if (tid == 0) {
            #pragma unroll
            for (int i = 0; i < 9; i++) g_part[blockIdx.x * 16 + i] = vals9[i];
        }
        grid_barrier(mygen);

        if (blockIdx.x == 0) {
            float pv[9];
            #pragma unroll
            for (int i = 0; i < 9; i++)
                pv[i] = (tid < NBLK) ? g_part[tid * 16 + i] : 0.0f;
            block_reduce<9>(pv, red);
            if (tid == 0) {
                float e = pv[8] * (1.0f / (2.0f * (float)M_ROWS));
                #pragma unroll
                for (int i = 0; i < 8; i++) g_cnew[i] = 0.25f / pv[i];  // v = 1/N
                g_stop = (e < SINK_THRESH || t >= SINK_MAX_ITER) ? 1 : 0;
            }
        }
        grid_barrier(mygen);

        int stop = g_stop;
        #pragma unroll
        for (int i = 0; i < 8; i++) { cp[i] = cm[i]; cm[i] = g_cnew[i]; }
        if (stop) break;
    }

    // ---- final: sim_op[b] = sum_m r_T[m] * sum_n c_T[n] K[m,n] sim[m,n] ----
    float ov[2] = {0.0f, 0.0f};
    if (active) {
        #pragma unroll
        for (int b = 0; b < 2; b++) {
            float s = 0.0f, a = 0.0f;
            #pragma unroll
            for (int n = 0; n < 4; n++) {
                s = fmaf(Kv[b * 4 + n], cp[b * 4 + n], s);
                a = fmaf(cm[b * 4 + n] * Kv[b * 4 + n], simv[b * 4 + n], a);
            }
            ov[b] = (uu / s) * a;
        }
    }
    block_reduce<2>(ov, red);
    if (tid == 0) {
        g_part[blockIdx.x * 16 + 0] = ov[0];
        g_part[blockIdx.x * 16 + 1] = ov[1];
    }
    grid_barrier(mygen);
    if (blockIdx.x == 0) {
        float pv[2];
        pv[0] = (tid < NBLK) ? g_part[tid * 16 + 0] : 0.0f;
        pv[1] = (tid < NBLK) ? g_part[tid * 16 + 1] : 0.0f;
        block_reduce<2>(pv, red);
        if (tid == 0) {
            float sc = expf(ls[0]);
            out[0] = sc * pv[0];
            out[1] = sc * pv[1];
        }
    }
}

extern "C" void kernel_launch(void* const* d_in, const int* in_sizes, int n_in,
                              void* d_out, int out_size) {
    const float* img = (const float*)d_in[0];
    const float* txt = (const float*)d_in[1];
    const float* ls  = (const float*)d_in[2];
    float* out = (float*)d_out;
    (void)in_sizes; (void)n_in; (void)out_size;

    mg_init<<<1, 1>>>();
    mg_fused<<<NBLK, NTHR>>>(img, txt, ls, out);
}

// round 5
// speedup vs baseline: 1.7683x; 1.0875x over previous
#include <cuda_runtime.h>

// ---------------------------------------------------------------------------
// MGPATH Sinkhorn-OT head, fused persistent kernel. R5 = R4 + fixed
// cross-half-warp combine in the butterfly reduction (the h=16 exchange the
// 16-value tree needs; R4 summed only half the dims per row).
// ---------------------------------------------------------------------------

#define M_ROWS 65536
#define D_DIM  1024
#define NBLK   148
#define NTHR   448
#define NWARP  14
#define NGROUPS 2048            // 65536 rows / 32 rows-per-warp-group
#define SINK_MAX_ITER 100
#define SINK_THRESH 0.01f

__device__ volatile float    g_part[NBLK * 16];
__device__ volatile float    g_cnew[8];
__device__ volatile int      g_stop;
__device__ unsigned          g_cnt;
__device__ volatile unsigned g_gen;

__global__ void mg_init() { g_cnt = 0u; g_gen = 0u; g_stop = 0; }

// sense-reversing grid barrier; all NBLK blocks co-resident (1/SM, 148 SMs)
__device__ __forceinline__ void grid_barrier(unsigned &mygen) {
    __syncthreads();
    if (threadIdx.x == 0) {
        __threadfence();
        unsigned prev = atomicAdd(&g_cnt, 1u);
        if (prev == NBLK - 1) {
            g_cnt = 0u;
            __threadfence();
            g_gen = mygen + 1u;
        } else {
            while (g_gen == mygen) { __nanosleep(32); }
        }
        __threadfence();
    }
    __syncthreads();
    mygen++;
}

template <int NV>
__device__ __forceinline__ void block_reduce(float* vals, float* red) {
    #pragma unroll
    for (int i = 0; i < NV; i++) {
        #pragma unroll
        for (int o = 16; o > 0; o >>= 1)
            vals[i] += __shfl_down_sync(0xffffffffu, vals[i], o);
    }
    int w = threadIdx.x >> 5, l = threadIdx.x & 31;
    if (l == 0) {
        #pragma unroll
        for (int i = 0; i < NV; i++) red[i * 16 + w] = vals[i];
    }
    __syncthreads();
    if (threadIdx.x < 32) {
        #pragma unroll
        for (int i = 0; i < NV; i++) {
            float x = (l < NWARP) ? red[i * 16 + l] : 0.0f;
            #pragma unroll
            for (int o = 8; o > 0; o >>= 1)
                x += __shfl_down_sync(0xffffffffu, x, o);
            vals[i] = x;
        }
    }
    __syncthreads();
}

__global__ void __launch_bounds__(NTHR, 1)
mg_fused(const float* __restrict__ img,
         const float* __restrict__ txt,
         const float* __restrict__ ls,
         float* __restrict__ out) {
    // v-major txt: txtS[v*1024 + d], v = c*4 + n, value = txt[(n*2+c)*D + d]
    __shared__ float txtS[8 * D_DIM];
    __shared__ float simP[NWARP * 32];
    __shared__ float red[9 * 16];

    const int tid  = threadIdx.x;
    const int lane = tid & 31;
    const int wid  = tid >> 5;

    for (int i = tid; i < 8 * D_DIM; i += NTHR) {
        int v = i >> 10, d = i & 1023;
        int n = v & 3, c = v >> 2;
        txtS[i] = txt[(n * 2 + c) * D_DIM + d];
    }
    __syncthreads();

    // round-robin: warp-slot wid*NBLK+blk owns one 32-row group
    const int rg = wid * NBLK + blockIdx.x;
    const bool active = (rg < NGROUPS);

    const ulonglong2* ts2 = reinterpret_cast<const ulonglong2*>(txtS);

    float simv[8] = {0.f, 0.f, 0.f, 0.f, 0.f, 0.f, 0.f, 0.f};

    if (active) {
        // lane-local base: group start + this lane's float4 column
        const float4* gp = reinterpret_cast<const float4*>(img)
                         + (size_t)rg * 32 * 256 + lane;

        // depth-4 circular register buffer over linear steps s = pass*8 + jj
        float4 buf[4][2];
        #pragma unroll
        for (int s = 0; s < 4; s++) {
            buf[s][0] = __ldcs(gp + 0 * 256 + s * 32);   // pass 0, row 0
            buf[s][1] = __ldcs(gp + 1 * 256 + s * 32);   // pass 0, row 1
        }

        #pragma unroll 1
        for (int pass = 0; pass < 16; pass++) {
            unsigned long long acc[2][8];
            #pragma unroll
            for (int g = 0; g < 2; g++)
                #pragma unroll
                for (int v = 0; v < 8; v++) acc[g][v] = 0ull;

            #pragma unroll
            for (int jj = 0; jj < 8; jj++) {
                float4 c0 = buf[jj & 3][0];
                float4 c1 = buf[jj & 3][1];

                // prefetch step s+4 (same circular slot jj&3)
                if (pass < 15 || jj < 4) {
                    int tp = pass + (jj >= 4 ? 1 : 0);
                    int tj = (jj + 4) & 7;
                    buf[jj & 3][0] = __ldcs(gp + (tp * 2 + 0) * 256 + tj * 32);
                    buf[jj & 3][1] = __ldcs(gp + (tp * 2 + 1) * 256 + tj * 32);
                }

                unsigned long long l0, h0, l1, h1;
                asm("mov.b64 %0, {%1, %2};" : "=l"(l0) : "f"(c0.x), "f"(c0.y));
                asm("mov.b64 %0, {%1, %2};" : "=l"(h0) : "f"(c0.z), "f"(c0.w));
                asm("mov.b64 %0, {%1, %2};" : "=l"(l1) : "f"(c1.x), "f"(c1.y));
                asm("mov.b64 %0, {%1, %2};" : "=l"(h1) : "f"(c1.z), "f"(c1.w));

                #pragma unroll
                for (int v = 0; v < 8; v++) {
                    ulonglong2 tv = ts2[v * 256 + jj * 32 + lane];
                    asm("fma.rn.f32x2 %0, %1, %2, %0;" : "+l"(acc[0][v]) : "l"(l0), "l"(tv.x));
                    asm("fma.rn.f32x2 %0, %1, %2, %0;" : "+l"(acc[0][v]) : "l"(h0), "l"(tv.y));
                    asm("fma.rn.f32x2 %0, %1, %2, %0;" : "+l"(acc[1][v]) : "l"(l1), "l"(tv.x));
                    asm("fma.rn.f32x2 %0, %1, %2, %0;" : "+l"(acc[1][v]) : "l"(h1), "l"(tv.y));
                }
            }

            // 16 partials (g*8+v): 4-round multi-value butterfly reduces
            // within each half-warp; the extra xor-16 combines the halves.
            float vals[16];
            #pragma unroll
            for (int g = 0; g < 2; g++)
                #pragma unroll
                for (int v = 0; v < 8; v++) {
                    float x, y;
                    asm("mov.b64 {%0, %1}, %2;" : "=f"(x), "=f"(y) : "l"(acc[g][v]));
                    vals[g * 8 + v] = x + y;
                }
            #pragma unroll
            for (int h = 8; h >= 1; h >>= 1) {
                bool up = (lane & h) != 0;
                #pragma unroll
                for (int i = 0; i < h; i++) {
                    float keep = up ? vals[i + h] : vals[i];
                    float send = up ? vals[i]     : vals[i + h];
                    vals[i] = keep + __shfl_xor_sync(0xffffffffu, send, h);
                }
            }
            // cross-half-warp combine: lane L now holds FULL value (L & 15)
            vals[0] += __shfl_xor_sync(0xffffffffu, vals[0], 16);

            // transpose via smem slab: row (pass*2+g) collects its 8 v's
            simP[wid * 32 + lane] = vals[0];
            __syncwarp();
            if ((lane >> 1) == pass) {
                int base = wid * 32 + (lane & 1) * 8;
                float4 s0 = *reinterpret_cast<float4*>(&simP[base]);
                float4 s1 = *reinterpret_cast<float4*>(&simP[base + 4]);
                simv[0] = s0.x; simv[1] = s0.y; simv[2] = s0.z; simv[3] = s0.w;
                simv[4] = s1.x; simv[5] = s1.y; simv[6] = s1.z; simv[7] = s1.w;
            }
            __syncwarp();
        }
    }

    // K = exp(-(1 - sim)/0.1); lane owns row rg*32 + lane
    float Kv[8];
    #pragma unroll
    for (int i = 0; i < 8; i++) Kv[i] = active ? expf((simv[i] - 1.0f) * 10.0f) : 0.0f;

    const float uu = 1.0f / (float)M_ROWS;
    float cm[8], cp[8];
    #pragma unroll
    for (int i = 0; i < 8; i++) { cm[i] = 1.0f; cp[i] = 1.0f; }

    // ---- Sinkhorn loop (c-only state; r recomputed from c each sweep) ----
    unsigned mygen = 0;
    int t = 0;
    for (;;) {
        t++;
        float vals9[9];
        if (active) {
            float err = 0.0f;
            float rr[2];
            #pragma unroll
            for (int b = 0; b < 2; b++) {
                float s = 0.0f, s2 = 0.0f;
                #pragma unroll
                for (int n = 0; n < 4; n++) {
                    s  = fmaf(Kv[b * 4 + n], cm[b * 4 + n], s);
                    s2 = fmaf(Kv[b * 4 + n], cp[b * 4 + n], s2);
                }
                float r    = uu / s;
                float rold = (t == 1) ? 1.0f : uu / s2;   // r0 = ones
                rr[b] = r;
                err += fabsf(r - rold);
            }
            #pragma unroll
            for (int b = 0; b < 2; b++)
                #pragma unroll
                for (int n = 0; n < 4; n++)
                    vals9[b * 4 + n] = Kv[b * 4 + n] * rr[b];
            vals9[8] = err;
        } else {
            #pragma unroll
            for (int i = 0; i < 9; i++) vals9[i] = 0.0f;
        }

        block_reduce<9>(vals9, red);
        if (tid == 0) {
            #pragma unroll
            for (int i = 0; i < 9; i++) g_part[blockIdx.x * 16 + i] = vals9[i];
        }
        grid_barrier(mygen);

        if (blockIdx.x == 0) {
            float pv[9];
            #pragma unroll
            for (int i = 0; i < 9; i++)
                pv[i] = (tid < NBLK) ? g_part[tid * 16 + i] : 0.0f;
            block_reduce<9>(pv, red);
            if (tid == 0) {
                float e = pv[8] * (1.0f / (2.0f * (float)M_ROWS));
                #pragma unroll
                for (int i = 0; i < 8; i++) g_cnew[i] = 0.25f / pv[i];  // v = 1/N
                g_stop = (e < SINK_THRESH || t >= SINK_MAX_ITER) ? 1 : 0;
            }
        }
        grid_barrier(mygen);

        int stop = g_stop;
        #pragma unroll
        for (int i = 0; i < 8; i++) { cp[i] = cm[i]; cm[i] = g_cnew[i]; }
        if (stop) break;
    }

    // ---- final: sim_op[b] = sum_m r_T[m] * sum_n c_T[n] K[m,n] sim[m,n] ----
    float ov[2] = {0.0f, 0.0f};
    if (active) {
        #pragma unroll
        for (int b = 0; b < 2; b++) {
            float s = 0.0f, a = 0.0f;
            #pragma unroll
            for (int n = 0; n < 4; n++) {
                s = fmaf(Kv[b * 4 + n], cp[b * 4 + n], s);
                a = fmaf(cm[b * 4 + n] * Kv[b * 4 + n], simv[b * 4 + n], a);
            }
            ov[b] = (uu / s) * a;
        }
    }
    block_reduce<2>(ov, red);
    if (tid == 0) {
        g_part[blockIdx.x * 16 + 0] = ov[0];
        g_part[blockIdx.x * 16 + 1] = ov[1];
    }
    grid_barrier(mygen);
    if (blockIdx.x == 0) {
        float pv[2];
        pv[0] = (tid < NBLK) ? g_part[tid * 16 + 0] : 0.0f;
        pv[1] = (tid < NBLK) ? g_part[tid * 16 + 1] : 0.0f;
        block_reduce<2>(pv, red);
        if (tid == 0) {
            float sc = expf(ls[0]);
            out[0] = sc * pv[0];
            out[1] = sc * pv[1];
        }
    }
}

extern "C" void kernel_launch(void* const* d_in, const int* in_sizes, int n_in,
                              void* d_out, int out_size) {
    const float* img = (const float*)d_in[0];
    const float* txt = (const float*)d_in[1];
    const float* ls  = (const float*)d_in[2];
    float* out = (float*)d_out;
    (void)in_sizes; (void)n_in; (void)out_size;

    mg_init<<<1, 1>>>();
    mg_fused<<<NBLK, NTHR>>>(img, txt, ls, out);
}

// round 6
// speedup vs baseline: 2.0853x; 1.1793x over previous
#include <cuda_runtime.h>

// ---------------------------------------------------------------------------
// MGPATH Sinkhorn-OT head, fused persistent kernel. R6:
// 4 rows/pass with v-pair-packed f32x2 accumulators (halves txt LDS per row),
// depth-4 x 4-row circular LDG prefetch (16 in flight, 112KB/SM),
// 3 grid barriers total (parity-double-buffered partials, redundant reduce).
// ---------------------------------------------------------------------------

#define M_ROWS 65536
#define D_DIM  1024
#define NBLK   148
#define NTHR   448
#define NWARP  14
#define NGROUPS 2048            // 65536 rows / 32 rows-per-warp-group
#define NPASS  8                // 4 rows per pass
#define SINK_MAX_ITER 100
#define SINK_THRESH 0.01f

__device__ volatile float    g_part[2][NBLK * 16];
__device__ unsigned          g_cnt;
__device__ volatile unsigned g_gen;

__global__ void mg_init() { g_cnt = 0u; g_gen = 0u; }

// sense-reversing grid barrier; all NBLK blocks co-resident (1/SM, 148 SMs)
__device__ __forceinline__ void grid_barrier(unsigned &mygen) {
    __syncthreads();
    if (threadIdx.x == 0) {
        __threadfence();
        unsigned prev = atomicAdd(&g_cnt, 1u);
        if (prev == NBLK - 1) {
            g_cnt = 0u;
            __threadfence();
            g_gen = mygen + 1u;
        } else {
            while (g_gen == mygen) { __nanosleep(32); }
        }
        __threadfence();
    }
    __syncthreads();
    mygen++;
}

template <int NV>
__device__ __forceinline__ void block_reduce(float* vals, float* red) {
    #pragma unroll
    for (int i = 0; i < NV; i++) {
        #pragma unroll
        for (int o = 16; o > 0; o >>= 1)
            vals[i] += __shfl_down_sync(0xffffffffu, vals[i], o);
    }
    int w = threadIdx.x >> 5, l = threadIdx.x & 31;
    if (l == 0) {
        #pragma unroll
        for (int i = 0; i < NV; i++) red[i * 16 + w] = vals[i];
    }
    __syncthreads();
    if (threadIdx.x < 32) {
        #pragma unroll
        for (int i = 0; i < NV; i++) {
            float x = (l < NWARP) ? red[i * 16 + l] : 0.0f;
            #pragma unroll
            for (int o = 8; o > 0; o >>= 1)
                x += __shfl_down_sync(0xffffffffu, x, o);
            vals[i] = x;
        }
    }
    __syncthreads();
}

__global__ void __launch_bounds__(NTHR, 1)
mg_fused(const float* __restrict__ img,
         const float* __restrict__ txt,
         const float* __restrict__ ls,
         float* __restrict__ out) {
    // txtP float4 at index jj*256 + dd*64 + h*32 + lane:
    //   = { txt_v(4h+0)[d], txt_v(4h+1)[d], txt_v(4h+2)[d], txt_v(4h+3)[d] }
    //   with d = jj*128 + lane*4 + dd, txt_v(v)[d] = txt[((v&3)*2 + (v>>2))*D + d]
    __shared__ float4 txtP[2048];
    __shared__ float  simP[NWARP * 32];
    __shared__ float  red[9 * 16];
    __shared__ float  bc[9];

    const int tid  = threadIdx.x;
    const int lane = tid & 31;
    const int wid  = tid >> 5;

    for (int f = tid; f < 2048; f += NTHR) {
        int jj = f >> 8, rem = f & 255, u = rem >> 5, ln = rem & 31;
        int dd = u >> 1, h = u & 1;
        int d = jj * 128 + ln * 4 + dd;
        float4 val;
        val.x = txt[(0 * 2 + h) * D_DIM + d];   // n=0, c=h
        val.y = txt[(1 * 2 + h) * D_DIM + d];   // n=1
        val.z = txt[(2 * 2 + h) * D_DIM + d];   // n=2
        val.w = txt[(3 * 2 + h) * D_DIM + d];   // n=3
        txtP[f] = val;
    }
    __syncthreads();

    // round-robin: warp-slot wid*NBLK+blk owns one 32-row group
    const int rg = wid * NBLK + blockIdx.x;
    const bool active = (rg < NGROUPS);

    const ulonglong2* ts2 = reinterpret_cast<const ulonglong2*>(txtP);

    float simv[8] = {0.f, 0.f, 0.f, 0.f, 0.f, 0.f, 0.f, 0.f};

    if (active) {
        const float4* gp = reinterpret_cast<const float4*>(img)
                         + (size_t)rg * 32 * 256 + lane;

        // depth-4 circular buffer over linear steps s = pass*8 + jj, 4 rows
        float4 buf[4][4];
        #pragma unroll
        for (int s = 0; s < 4; s++)
            #pragma unroll
            for (int g = 0; g < 4; g++)
                buf[s][g] = __ldcs(gp + g * 256 + s * 32);   // pass 0

        #pragma unroll 1
        for (int pass = 0; pass < NPASS; pass++) {
            unsigned long long acc[4][4];
            #pragma unroll
            for (int g = 0; g < 4; g++)
                #pragma unroll
                for (int vp = 0; vp < 4; vp++) acc[g][vp] = 0ull;

            #pragma unroll
            for (int jj = 0; jj < 8; jj++) {
                float4 c[4];
                #pragma unroll
                for (int g = 0; g < 4; g++) c[g] = buf[jj & 3][g];

                // prefetch step s+4 into the vacated circular slot
                if (pass < NPASS - 1 || jj < 4) {
                    int s  = pass * 8 + jj + 4;
                    int tp = s >> 3, tj = s & 7;
                    #pragma unroll
                    for (int g = 0; g < 4; g++)
                        buf[jj & 3][g] = __ldcs(gp + (tp * 4 + g) * 256 + tj * 32);
                }

                #pragma unroll
                for (int dd = 0; dd < 4; dd++) {
                    ulonglong2 tvA = ts2[jj * 256 + dd * 64 + lane];       // v0..3
                    ulonglong2 tvB = ts2[jj * 256 + dd * 64 + 32 + lane];  // v4..7
                    #pragma unroll
                    for (int g = 0; g < 4; g++) {
                        float xv = (dd == 0) ? c[g].x : (dd == 1) ? c[g].y
                                 : (dd == 2) ? c[g].z : c[g].w;
                        unsigned long long xx;
                        asm("mov.b64 %0, {%1, %1};" : "=l"(xx) : "f"(xv));
                        asm("fma.rn.f32x2 %0, %1, %2, %0;" : "+l"(acc[g][0]) : "l"(xx), "l"(tvA.x));
                        asm("fma.rn.f32x2 %0, %1, %2, %0;" : "+l"(acc[g][1]) : "l"(xx), "l"(tvA.y));
                        asm("fma.rn.f32x2 %0, %1, %2, %0;" : "+l"(acc[g][2]) : "l"(xx), "l"(tvB.x));
                        asm("fma.rn.f32x2 %0, %1, %2, %0;" : "+l"(acc[g][3]) : "l"(xx), "l"(tvB.y));
                    }
                }
            }

            // unpack 32 partials: vals[g*8 + vp*2 + {0,1}] = (lo,hi) of acc
            float vals[32];
            #pragma unroll
            for (int g = 0; g < 4; g++)
                #pragma unroll
                for (int vp = 0; vp < 4; vp++) {
                    float x, y;
                    asm("mov.b64 {%0, %1}, %2;" : "=f"(x), "=f"(y) : "l"(acc[g][vp]));
                    vals[g * 8 + vp * 2]     = x;
                    vals[g * 8 + vp * 2 + 1] = y;
                }
            // 5-round multi-value butterfly: lane L ends holding value L
            #pragma unroll
            for (int h = 16; h >= 1; h >>= 1) {
                bool up = (lane & h) != 0;
                #pragma unroll
                for (int i = 0; i < h; i++) {
                    float keep = up ? vals[i + h] : vals[i];
                    float send = up ? vals[i]     : vals[i + h];
                    vals[i] = keep + __shfl_xor_sync(0xffffffffu, send, h);
                }
            }
            // transpose via smem slab: row (pass*4+g) collects its 8 v's
            simP[wid * 32 + lane] = vals[0];
            __syncwarp();
            if ((lane >> 2) == pass) {
                int base = wid * 32 + (lane & 3) * 8;
                float4 s0 = *reinterpret_cast<float4*>(&simP[base]);
                float4 s1 = *reinterpret_cast<float4*>(&simP[base + 4]);
                simv[0] = s0.x; simv[1] = s0.y; simv[2] = s0.z; simv[3] = s0.w;
                simv[4] = s1.x; simv[5] = s1.y; simv[6] = s1.z; simv[7] = s1.w;
            }
            __syncwarp();
        }
    }

    // K = exp(-(1 - sim)/0.1); lane owns row rg*32 + lane
    float Kv[8];
    #pragma unroll
    for (int i = 0; i < 8; i++) Kv[i] = active ? expf((simv[i] - 1.0f) * 10.0f) : 0.0f;

    const float uu = 1.0f / (float)M_ROWS;
    float cm[8], cp[8];
    #pragma unroll
    for (int i = 0; i < 8; i++) { cm[i] = 1.0f; cp[i] = 1.0f; }

    // ---- Sinkhorn loop: 1 grid barrier per iteration (parity slabs,
    //      every block redundantly reduces all partials) ----
    unsigned mygen = 0;
    int t = 0;
    for (;;) {
        t++;
        float vals9[9];
        if (active) {
            float err = 0.0f;
            float rr[2];
            #pragma unroll
            for (int b = 0; b < 2; b++) {
                float s = 0.0f, s2 = 0.0f;
                #pragma unroll
                for (int n = 0; n < 4; n++) {
                    s  = fmaf(Kv[b * 4 + n], cm[b * 4 + n], s);
                    s2 = fmaf(Kv[b * 4 + n], cp[b * 4 + n], s2);
                }
                float r    = uu / s;
                float rold = (t == 1) ? 1.0f : uu / s2;   // r0 = ones
                rr[b] = r;
                err += fabsf(r - rold);
            }
            #pragma unroll
            for (int b = 0; b < 2; b++)
                #pragma unroll
                for (int n = 0; n < 4; n++)
                    vals9[b * 4 + n] = Kv[b * 4 + n] * rr[b];
            vals9[8] = err;
        } else {
            #pragma unroll
            for (int i = 0; i < 9; i++) vals9[i] = 0.0f;
        }

        block_reduce<9>(vals9, red);
        const int sl = t & 1;
        if (tid == 0) {
            #pragma unroll
            for (int i = 0; i < 9; i++) g_part[sl][blockIdx.x * 16 + i] = vals9[i];
        }
        grid_barrier(mygen);

        // every block reduces all partials (identical result everywhere)
        float pv[9];
        #pragma unroll
        for (int i = 0; i < 9; i++)
            pv[i] = (tid < NBLK) ? g_part[sl][tid * 16 + i] : 0.0f;
        block_reduce<9>(pv, red);
        if (tid == 0) {
            float e = pv[8] * (1.0f / (2.0f * (float)M_ROWS));
            #pragma unroll
            for (int i = 0; i < 8; i++) bc[i] = 0.25f / pv[i];   // v = 1/N
            bc[8] = (e < SINK_THRESH || t >= SINK_MAX_ITER) ? 1.0f : 0.0f;
        }
        __syncthreads();
        int stop = (bc[8] != 0.0f);
        #pragma unroll
        for (int i = 0; i < 8; i++) { cp[i] = cm[i]; cm[i] = bc[i]; }
        if (stop) break;
    }

    // ---- final: sim_op[b] = sum_m r_T[m] * sum_n c_T[n] K[m,n] sim[m,n] ----
    float ov[2] = {0.0f, 0.0f};
    if (active) {
        #pragma unroll
        for (int b = 0; b < 2; b++) {
            float s = 0.0f, a = 0.0f;
            #pragma unroll
            for (int n = 0; n < 4; n++) {
                s = fmaf(Kv[b * 4 + n], cp[b * 4 + n], s);
                a = fmaf(cm[b * 4 + n] * Kv[b * 4 + n], simv[b * 4 + n], a);
            }
            ov[b] = (uu / s) * a;
        }
    }
    block_reduce<2>(ov, red);
    const int slf = (t + 1) & 1;
    if (tid == 0) {
        g_part[slf][blockIdx.x * 16 + 0] = ov[0];
        g_part[slf][blockIdx.x * 16 + 1] = ov[1];
    }
    grid_barrier(mygen);
    if (blockIdx.x == 0) {
        float pv[2];
        pv[0] = (tid < NBLK) ? g_part[slf][tid * 16 + 0] : 0.0f;
        pv[1] = (tid < NBLK) ? g_part[slf][tid * 16 + 1] : 0.0f;
        block_reduce<2>(pv, red);
        if (tid == 0) {
            float sc = expf(ls[0]);
            out[0] = sc * pv[0];
            out[1] = sc * pv[1];
        }
    }
}

extern "C" void kernel_launch(void* const* d_in, const int* in_sizes, int n_in,
                              void* d_out, int out_size) {
    const float* img = (const float*)d_in[0];
    const float* txt = (const float*)d_in[1];
    const float* ls  = (const float*)d_in[2];
    float* out = (float*)d_out;
    (void)in_sizes; (void)n_in; (void)out_size;

    mg_init<<<1, 1>>>();
    mg_fused<<<NBLK, NTHR>>>(img, txt, ls, out);
}